// round 5
// baseline (speedup 1.0000x reference)
#include <cuda_runtime.h>
#include <cuda_bf16.h>
#include <cstdint>

#define DIM 16777216
#define TPB 256

__device__ __forceinline__ float spu_f(float z) {
    // z >= 0 : z*z - 0.5
    // z <  0 : sigmoid(-z) - 1 = -sigmoid(z) = -e^z / (1 + e^z)
    float pos = fmaf(z, z, -0.5f);
    float e = __expf(z);
    float neg = -__fdividef(e, 1.0f + e);
    return (z >= 0.0f) ? pos : neg;
}

// 256-bit global load (sm_100+): 8 consecutive f32
__device__ __forceinline__ void ldg256(const float* p, float* v) {
    asm volatile("ld.global.nc.v8.b32 {%0,%1,%2,%3,%4,%5,%6,%7}, [%8];"
                 : "=f"(v[0]), "=f"(v[1]), "=f"(v[2]), "=f"(v[3]),
                   "=f"(v[4]), "=f"(v[5]), "=f"(v[6]), "=f"(v[7])
                 : "l"(p));
}

// 256-bit global store (sm_100+)
__device__ __forceinline__ void stg256(float* p, const float* v) {
    asm volatile("st.global.v8.b32 [%0], {%1,%2,%3,%4,%5,%6,%7,%8};"
                 :: "l"(p),
                    "f"(v[0]), "f"(v[1]), "f"(v[2]), "f"(v[3]),
                    "f"(v[4]), "f"(v[5]), "f"(v[6]), "f"(v[7])
                 : "memory");
}

__global__ void __launch_bounds__(TPB, 8)
spu_kernel(const float* __restrict__ x,
           const float* __restrict__ l,
           const float* __restrict__ u,
           float* __restrict__ out_x,
           float* __restrict__ out_l,
           float* __restrict__ out_u)
{
    long long base = (long long)(blockIdx.x * TPB + threadIdx.x) * 8;

    float xv[8], lv[8], uv[8];
    ldg256(x + base, xv);
    ldg256(l + base, lv);
    ldg256(u + base, uv);

    float xo[8], lo[8], uo[8];

    #pragma unroll
    for (int k = 0; k < 8; ++k) {
        float xs = xv[k];
        float ls = lv[k];
        float us = uv[k];

        float sx = spu_f(xs);
        float sl = spu_f(ls);
        float su = spu_f(us);

        // l_out = l>=0 ? spu(l) : (u<=0 ? spu(u) : -0.5)
        lo[k] = (ls >= 0.0f) ? sl : ((us <= 0.0f) ? su : -0.5f);
        // u_out = u<=0 ? spu(l) : spu(u)
        uo[k] = (us <= 0.0f) ? sl : su;
        xo[k] = sx;
    }

    stg256(out_x + base, xo);
    stg256(out_l + base, lo);
    stg256(out_u + base, uo);
}

extern "C" void kernel_launch(void* const* d_in, const int* in_sizes, int n_in,
                              void* d_out, int out_size) {
    const float* x = (const float*)d_in[0];
    const float* l = (const float*)d_in[1];
    const float* u = (const float*)d_in[2];

    float* out = (float*)d_out;
    float* out_x = out;
    float* out_l = out + DIM;
    float* out_u = out + 2 * DIM;

    const int n_threads = DIM / 8;            // 2,097,152 threads, 8 floats each
    const int blocks = n_threads / TPB;       // 8,192
    spu_kernel<<<blocks, TPB>>>(x, l, u, out_x, out_l, out_u);
}